// round 8
// baseline (speedup 1.0000x reference)
#include <cuda_runtime.h>
#include <cuda_bf16.h>

#define N  8192
#define B  4096                  // time buckets (avg 2 elements/bucket)
#define T  1024                  // single block of 1024 threads
#define PJ (N / T)               // 8 elements per thread

// Shared layout (dynamic): cnt[B] off[B] cur[B] bsum[B] pre[B] st[N] se[N]
#define SMEM_BYTES ((5 * B + 2 * N) * 4)   // 144 KB

// O(N) Cox loss in ONE block:
//  1. bucket counts + per-bucket exp-sums (smem atomics)
//  2. fused block scan: exclusive prefix of counts (-> offsets) and of
//     bucket sums (-> cross-bucket suffix via S - pre - bsum)
//  3. counting-sort scatter of (t, e) into bucket-contiguous smem arrays
//  4. per-i: rs = suffix(bucket) + exact in-bucket compare-sum; loss; reduce
__global__ void __launch_bounds__(T, 1)
cox_bucket_kernel(const float* __restrict__ hazard,
                  const float* __restrict__ time,
                  const float* __restrict__ censor,
                  float* __restrict__ out)
{
    extern __shared__ int smem_raw[];
    int*   cnt  = smem_raw;            // [B] bucket counts
    int*   off  = cnt  + B;            // [B] bucket start offsets
    int*   cur  = off  + B;            // [B] scatter cursors
    float* bsum = (float*)(cur + B);   // [B] per-bucket sum of exp(hazard)
    float* pre  = bsum + B;            // [B] exclusive prefix of bsum
    float* st   = pre  + B;            // [N] sorted times
    float* se   = st   + N;            // [N] sorted exp values

    __shared__ int   wti[32];
    __shared__ float wtf[32];
    __shared__ float S_tot;

    const int tid  = threadIdx.x;
    const int lane = tid & 31;
    const int w    = tid >> 5;

    // ---- Phase 0: zero counts / sums ----
#pragma unroll
    for (int q = 0; q < B / T; ++q) {
        cnt[q * T + tid]  = 0;
        bsum[q * T + tid] = 0.0f;
    }
    __syncthreads();

    // ---- Phase 1: load, exp, count, bucket-sum (coalesced j = k*T+tid) ----
    float tj[PJ], ej[PJ];
#pragma unroll
    for (int k = 0; k < PJ; ++k) {
        const int j = k * T + tid;
        tj[k] = time[j];
        ej[k] = expf(hazard[j]);
        int b = (int)(tj[k] * (float)B);
        b = min(b, B - 1);
        atomicAdd(&cnt[b], 1);
        atomicAdd(&bsum[b], ej[k]);
    }
    __syncthreads();

    // ---- Phase 2: fused exclusive scans (cnt -> off, bsum -> pre) ----
    // Each thread owns 4 consecutive buckets.
    int c4[4]; float f4[4];
    int li = 0; float lf = 0.0f;
#pragma unroll
    for (int q = 0; q < 4; ++q) {
        c4[q] = cnt[tid * 4 + q];
        f4[q] = bsum[tid * 4 + q];
        li += c4[q]; lf += f4[q];
    }
    int si = li; float sf = lf;                       // warp inclusive scan
#pragma unroll
    for (int o = 1; o < 32; o <<= 1) {
        int   ai = __shfl_up_sync(0xffffffffu, si, o);
        float af = __shfl_up_sync(0xffffffffu, sf, o);
        if (lane >= o) { si += ai; sf += af; }
    }
    if (lane == 31) { wti[w] = si; wtf[w] = sf; }
    __syncthreads();
    if (w == 0) {                                     // scan the 32 warp totals
        int vi = wti[lane]; float vf = wtf[lane];
#pragma unroll
        for (int o = 1; o < 32; o <<= 1) {
            int   ai = __shfl_up_sync(0xffffffffu, vi, o);
            float af = __shfl_up_sync(0xffffffffu, vf, o);
            if (lane >= o) { vi += ai; vf += af; }
        }
        wti[lane] = vi; wtf[lane] = vf;               // inclusive warp totals
        if (lane == 31) S_tot = vf;                   // grand total of exp
    }
    __syncthreads();
    int   basei = (w ? wti[w - 1] : 0)   + (si - li); // exclusive base
    float basef = (w ? wtf[w - 1] : 0.f) + (sf - lf);
#pragma unroll
    for (int q = 0; q < 4; ++q) {
        off[tid * 4 + q] = basei;
        cur[tid * 4 + q] = basei;
        pre[tid * 4 + q] = basef;
        basei += c4[q]; basef += f4[q];
    }
    __syncthreads();

    // ---- Phase 3: counting-sort scatter of (t, e) ----
#pragma unroll
    for (int k = 0; k < PJ; ++k) {
        int b = (int)(tj[k] * (float)B);
        b = min(b, B - 1);
        const int p = atomicAdd(&cur[b], 1);
        st[p] = tj[k];
        se[p] = ej[k];
    }
    __syncthreads();

    // ---- Phase 4: per-i risk sum + loss term ----
    const float S = S_tot;
    float acc = 0.0f;
#pragma unroll
    for (int k = 0; k < PJ; ++k) {
        const int   i  = k * T + tid;
        const float ti = tj[k];
        int b = (int)(ti * (float)B);
        b = min(b, B - 1);
        float rs = S - pre[b] - bsum[b];              // all buckets above b (exact set)
        const int p0 = off[b];
        const int n  = cnt[b];                        // avg 2
        for (int p = p0; p < p0 + n; ++p)
            if (st[p] >= ti) rs += se[p];             // exact in-bucket compare
        acc += (hazard[i] - logf(rs)) * censor[i];
    }

    // ---- Phase 5: block reduction ----
    __syncthreads();                                  // smem arrays now dead
    float* red = (float*)cnt;                         // reuse as scratch
    red[tid] = acc;
    __syncthreads();
#pragma unroll
    for (int s = T / 2; s >= 32; s >>= 1) {
        if (tid < s) red[tid] += red[tid + s];
        __syncthreads();
    }
    if (tid < 32) {
        float v = red[tid];
#pragma unroll
        for (int o = 16; o > 0; o >>= 1)
            v += __shfl_down_sync(0xffffffffu, v, o);
        if (tid == 0) out[0] = -v / (float)N;
    }
}

extern "C" void kernel_launch(void* const* d_in, const int* in_sizes, int n_in,
                              void* d_out, int out_size)
{
    const float* hazard = (const float*)d_in[0];
    const float* time_  = (const float*)d_in[1];
    const float* censor = (const float*)d_in[2];
    float* out = (float*)d_out;

    static int attr_done = 0;
    if (!attr_done) {
        cudaFuncSetAttribute(cox_bucket_kernel,
                             cudaFuncAttributeMaxDynamicSharedMemorySize, SMEM_BYTES);
        attr_done = 1;
    }
    cox_bucket_kernel<<<1, T, SMEM_BYTES>>>(hazard, time_, censor, out);
}